// round 3
// baseline (speedup 1.0000x reference)
#include <cuda_runtime.h>

// Problem constants
#define BB 2048
#define TT 2
#define NTOK 64
#define CDIM 256
#define NH 8
#define HD 32

// Scratch (device globals; allocation APIs are forbidden)
__device__ float g_q[(size_t)BB * NTOK * CDIM];
__device__ float g_kv[(size_t)BB * TT * NTOK * 2 * CDIM];
__device__ float g_attn[(size_t)BB * TT * NTOK * CDIM];

// ---- packed fp32x2 helpers (Blackwell FFMA2 — ptxas never auto-fuses) ----
__device__ __forceinline__ unsigned long long pack2(float x, float y) {
    unsigned long long r;
    asm("mov.b64 %0, {%1, %2};" : "=l"(r) : "f"(x), "f"(y));
    return r;
}
__device__ __forceinline__ void ffma2(unsigned long long& d,
                                      unsigned long long a, unsigned long long b) {
    asm("fma.rn.f32x2 %0, %1, %2, %0;" : "+l"(d) : "l"(a), "l"(b));
}
__device__ __forceinline__ float2 unpack2(unsigned long long v) {
    float2 f;
    asm("mov.b64 {%0, %1}, %2;" : "=f"(f.x), "=f"(f.y) : "l"(v));
    return f;
}

// ---------------------------------------------------------------------------
// SGEMM: C[M,N] = A[M,K] @ W[N,K]^T + bias[N]   (both K-contiguous)
// 128x128 tile, BK=8, 256 threads, 8x8 micro-tile via packed f32x2 (8x4 accs).
// ---------------------------------------------------------------------------
__global__ __launch_bounds__(256) void sgemm_nt(
    const float* __restrict__ A, const float* __restrict__ W,
    const float* __restrict__ bias, float* __restrict__ C,
    int M, int N, int K)
{
    __shared__ float As[8][128];
    __shared__ float Ws[8][128];

    const int tid = threadIdx.x;
    const int bm = blockIdx.y * 128;
    const int bn = blockIdx.x * 128;

    const int lr = tid >> 1;
    const int lc = (tid & 1) * 4;
    const float* Ap = A + (size_t)(bm + lr) * K + lc;
    const float* Wp = W + (size_t)(bn + lr) * K + lc;

    const int tr = (tid >> 4) * 8;
    const int tc = (tid & 15) * 8;

    unsigned long long acc[8][4];
#pragma unroll
    for (int i = 0; i < 8; i++)
#pragma unroll
        for (int j = 0; j < 4; j++) acc[i][j] = 0ull;

    for (int k0 = 0; k0 < K; k0 += 8) {
        float4 a4 = *reinterpret_cast<const float4*>(Ap);
        float4 w4 = *reinterpret_cast<const float4*>(Wp);
        As[lc + 0][lr] = a4.x; As[lc + 1][lr] = a4.y;
        As[lc + 2][lr] = a4.z; As[lc + 3][lr] = a4.w;
        Ws[lc + 0][lr] = w4.x; Ws[lc + 1][lr] = w4.y;
        Ws[lc + 2][lr] = w4.z; Ws[lc + 3][lr] = w4.w;
        __syncthreads();

#pragma unroll
        for (int k = 0; k < 8; k++) {
            // B fragment: 4 packed pairs (64-bit shared loads, 32B-aligned)
            unsigned long long bf[4];
            const unsigned long long* wrow =
                reinterpret_cast<const unsigned long long*>(&Ws[k][tc]);
#pragma unroll
            for (int j = 0; j < 4; j++) bf[j] = wrow[j];
#pragma unroll
            for (int i = 0; i < 8; i++) {
                float a = As[k][tr + i];
                unsigned long long a2 = pack2(a, a);
#pragma unroll
                for (int j = 0; j < 4; j++) ffma2(acc[i][j], a2, bf[j]);
            }
        }
        __syncthreads();
        Ap += 8;
        Wp += 8;
    }

#pragma unroll
    for (int i = 0; i < 8; i++) {
        float* Cp = C + (size_t)(bm + tr + i) * N + bn + tc;
        float2 p0 = unpack2(acc[i][0]);
        float2 p1 = unpack2(acc[i][1]);
        float2 p2 = unpack2(acc[i][2]);
        float2 p3 = unpack2(acc[i][3]);
        float4 v0, v1;
        v0.x = p0.x + bias[bn + tc + 0]; v0.y = p0.y + bias[bn + tc + 1];
        v0.z = p1.x + bias[bn + tc + 2]; v0.w = p1.y + bias[bn + tc + 3];
        v1.x = p2.x + bias[bn + tc + 4]; v1.y = p2.y + bias[bn + tc + 5];
        v1.z = p3.x + bias[bn + tc + 6]; v1.w = p3.y + bias[bn + tc + 7];
        *reinterpret_cast<float4*>(Cp)     = v0;
        *reinterpret_cast<float4*>(Cp + 4) = v1;
    }
}

// ---------------------------------------------------------------------------
// Attention: one block per (b, t, h), 64 threads = one query row each.
// f32x2 packed QK and PV inner loops.
// ---------------------------------------------------------------------------
__global__ __launch_bounds__(64) void attn_kernel(const float* __restrict__ rpb)
{
    __shared__ float4 sK[512];       // 64 rows x 8 float4
    __shared__ float4 sV[512];
    __shared__ float  sL[64 * 65];   // logits, padded to avoid bank conflicts

    const int bx = blockIdx.x;
    const int h = bx & 7;
    const int t = (bx >> 3) & 1;
    const int b = bx >> 4;
    const int n = threadIdx.x;

    const float* kb = g_kv + (size_t)((b * 2 + t) * 64) * 512 + h * 32;
    for (int i = n; i < 512; i += 64) {
        int r = i >> 3, c = i & 7;
        sK[i] = *reinterpret_cast<const float4*>(kb + (size_t)r * 512 + c * 4);
        sV[i] = *reinterpret_cast<const float4*>(kb + 256 + (size_t)r * 512 + c * 4);
    }

    // q row -> 16 packed pairs (pre-scaled)
    const float scale = 0.17677669529663687f;  // 32^-0.5
    unsigned long long q2[16];
    const float* qb = g_q + (size_t)(b * 64 + n) * 256 + h * 32;
#pragma unroll
    for (int c = 0; c < 8; c++) {
        float4 f = *reinterpret_cast<const float4*>(qb + c * 4);
        q2[2 * c + 0] = pack2(f.x * scale, f.y * scale);
        q2[2 * c + 1] = pack2(f.z * scale, f.w * scale);
    }
    __syncthreads();

    // logits + running max. bias idx = (ni-mi+7)*15 + (nj-mj+7)
    const int base_idx = ((n >> 3) + 7) * 15 + ((n & 7) + 7);
    float mx = -1e30f;
    float* myL = &sL[n * 65];
#pragma unroll 4
    for (int m = 0; m < 64; m++) {
        const unsigned long long* kr =
            reinterpret_cast<const unsigned long long*>(&sK[m * 8]);
        unsigned long long a0 = 0ull, a1 = 0ull, a2 = 0ull, a3 = 0ull;
#pragma unroll
        for (int c = 0; c < 4; c++) {
            ffma2(a0, q2[4 * c + 0], kr[4 * c + 0]);
            ffma2(a1, q2[4 * c + 1], kr[4 * c + 1]);
            ffma2(a2, q2[4 * c + 2], kr[4 * c + 2]);
            ffma2(a3, q2[4 * c + 3], kr[4 * c + 3]);
        }
        float2 f0 = unpack2(a0), f1 = unpack2(a1), f2 = unpack2(a2), f3 = unpack2(a3);
        int idx = base_idx - ((m >> 3) * 15 + (m & 7));
        float s = ((f0.x + f0.y) + (f1.x + f1.y)) + ((f2.x + f2.y) + (f3.x + f3.y))
                  + __ldg(&rpb[idx * 8 + h]);
        mx = fmaxf(mx, s);
        myL[m] = s;
    }

    // exp + sum
    float sum0 = 0.f, sum1 = 0.f;
#pragma unroll 4
    for (int m = 0; m < 64; m += 2) {
        float e0 = __expf(myL[m] - mx);
        float e1 = __expf(myL[m + 1] - mx);
        myL[m] = e0; myL[m + 1] = e1;
        sum0 += e0; sum1 += e1;
    }
    float inv = 1.0f / (sum0 + sum1);

    // PV (packed)
    unsigned long long o2[16];
#pragma unroll
    for (int c = 0; c < 16; c++) o2[c] = 0ull;
#pragma unroll 2
    for (int m = 0; m < 64; m++) {
        float w = myL[m];
        unsigned long long w2 = pack2(w, w);
        const unsigned long long* vr =
            reinterpret_cast<const unsigned long long*>(&sV[m * 8]);
#pragma unroll
        for (int c = 0; c < 16; c++) ffma2(o2[c], w2, vr[c]);
    }

    float* ob = g_attn + (size_t)((b * 2 + t) * 64 + n) * 256 + h * 32;
#pragma unroll
    for (int c = 0; c < 8; c++) {
        float2 pa = unpack2(o2[2 * c + 0]);
        float2 pb = unpack2(o2[2 * c + 1]);
        float4 v;
        v.x = pa.x * inv; v.y = pa.y * inv;
        v.z = pb.x * inv; v.w = pb.y * inv;
        *reinterpret_cast<float4*>(ob + c * 4) = v;
    }
}

// ---------------------------------------------------------------------------
extern "C" void kernel_launch(void* const* d_in, const int* in_sizes, int n_in,
                              void* d_out, int out_size)
{
    const float* x      = (const float*)d_in[0];
    const float* memory = (const float*)d_in[1];
    const float* q_w    = (const float*)d_in[2];
    const float* q_b    = (const float*)d_in[3];
    const float* kv_w   = (const float*)d_in[4];
    const float* kv_b   = (const float*)d_in[5];
    const float* proj_w = (const float*)d_in[6];
    const float* proj_b = (const float*)d_in[7];
    const float* rpb    = (const float*)d_in[8];
    float* out = (float*)d_out;

    float *pq, *pkv, *pattn;
    cudaGetSymbolAddress((void**)&pq, g_q);
    cudaGetSymbolAddress((void**)&pkv, g_kv);
    cudaGetSymbolAddress((void**)&pattn, g_attn);

    sgemm_nt<<<dim3(2, 1024), 256>>>(x, q_w, q_b, pq, BB * NTOK, CDIM, CDIM);
    sgemm_nt<<<dim3(4, 2048), 256>>>(memory, kv_w, kv_b, pkv, BB * TT * NTOK, 2 * CDIM, CDIM);
    attn_kernel<<<BB * TT * NH, 64>>>(rpb);
    sgemm_nt<<<dim3(2, 2048), 256>>>(pattn, proj_w, proj_b, out, BB * TT * NTOK, CDIM, CDIM);
}

// round 6
// speedup vs baseline: 2.0584x; 2.0584x over previous
#include <cuda_runtime.h>
#include <cstdint>

// Problem constants
#define BB 2048
#define TT 2
#define NTOK 64
#define CDIM 256
#define NH 8
#define HD 32

// Scratch (device globals; allocation APIs are forbidden)
__device__ float g_q[(size_t)BB * NTOK * CDIM];
__device__ float g_kv[(size_t)BB * TT * NTOK * 2 * CDIM];
__device__ float g_attn[(size_t)BB * TT * NTOK * CDIM];

// ---- tf32 helpers -----------------------------------------------------------
__device__ __forceinline__ uint32_t f2tf32(float f) {
    uint32_t r;
    asm("cvt.rna.tf32.f32 %0, %1;" : "=r"(r) : "f"(f));
    return r;
}
__device__ __forceinline__ void mma_tf32(float c[4], const uint32_t a[4],
                                         const uint32_t b[2]) {
    asm("mma.sync.aligned.m16n8k8.row.col.f32.tf32.tf32.f32 "
        "{%0,%1,%2,%3}, {%4,%5,%6,%7}, {%8,%9}, {%0,%1,%2,%3};"
        : "+f"(c[0]), "+f"(c[1]), "+f"(c[2]), "+f"(c[3])
        : "r"(a[0]), "r"(a[1]), "r"(a[2]), "r"(a[3]), "r"(b[0]), "r"(b[1]));
}

// ---------------------------------------------------------------------------
// TF32 tensor-core GEMM: C[M,N] = A[M,K] @ W[N,K]^T + bias[N]
// 128x128 block tile, BK=32, 256 threads (8 warps as 2M x 4N, 64x32 warp tile).
// Smem m-major, row stride 36 words -> conflict-free fragment loads
// (bank = 4*g + tig, all 32 lanes distinct).
// ---------------------------------------------------------------------------
__global__ __launch_bounds__(256, 2) void gemm_tf32(
    const float* __restrict__ A, const float* __restrict__ W,
    const float* __restrict__ bias, float* __restrict__ C,
    int M, int N, int K)
{
    __shared__ uint32_t As[128][36];
    __shared__ uint32_t Ws[128][36];

    const int tid  = threadIdx.x;
    const int wid  = tid >> 5;
    const int lane = tid & 31;
    const int g    = lane >> 2;     // groupID (0..7)
    const int tig  = lane & 3;      // thread-in-group (0..3)
    const int bm = blockIdx.y * 128;
    const int bn = blockIdx.x * 128;
    const int warp_m = (wid & 1) * 64;
    const int warp_n = (wid >> 1) * 32;

    // staging: thread handles rows (tid>>3)+32*it, float4 k-chunk (tid&7)
    const int sr  = tid >> 3;   // 0..31
    const int sk4 = tid & 7;    // 0..7

    float acc[4][4][4];
#pragma unroll
    for (int i = 0; i < 4; i++)
#pragma unroll
        for (int j = 0; j < 4; j++)
#pragma unroll
            for (int r = 0; r < 4; r++) acc[i][j][r] = 0.0f;

    for (int k0 = 0; k0 < K; k0 += 32) {
#pragma unroll
        for (int it = 0; it < 4; it++) {
            int r = sr + it * 32;
            float4 a4 = *reinterpret_cast<const float4*>(
                A + (size_t)(bm + r) * K + k0 + sk4 * 4);
            float4 w4 = *reinterpret_cast<const float4*>(
                W + (size_t)(bn + r) * K + k0 + sk4 * 4);
            uint4 at = make_uint4(f2tf32(a4.x), f2tf32(a4.y), f2tf32(a4.z), f2tf32(a4.w));
            uint4 wt = make_uint4(f2tf32(w4.x), f2tf32(w4.y), f2tf32(w4.z), f2tf32(w4.w));
            *reinterpret_cast<uint4*>(&As[r][sk4 * 4]) = at;
            *reinterpret_cast<uint4*>(&Ws[r][sk4 * 4]) = wt;
        }
        __syncthreads();

#pragma unroll
        for (int kk = 0; kk < 4; kk++) {
            uint32_t af[4][4], bf[4][2];
            const int kb = kk * 8;
#pragma unroll
            for (int i = 0; i < 4; i++) {
                int row = warp_m + i * 16;
                af[i][0] = As[row + g][kb + tig];
                af[i][1] = As[row + g + 8][kb + tig];
                af[i][2] = As[row + g][kb + tig + 4];
                af[i][3] = As[row + g + 8][kb + tig + 4];
            }
#pragma unroll
            for (int j = 0; j < 4; j++) {
                int col = warp_n + j * 8 + g;
                bf[j][0] = Ws[col][kb + tig];
                bf[j][1] = Ws[col][kb + tig + 4];
            }
#pragma unroll
            for (int i = 0; i < 4; i++)
#pragma unroll
                for (int j = 0; j < 4; j++)
                    mma_tf32(acc[i][j], af[i], bf[j]);
        }
        __syncthreads();
    }

    // epilogue: C frag mapping c0:(g, 2tig) c1:(g, 2tig+1) c2/c3:(g+8, ...)
#pragma unroll
    for (int j = 0; j < 4; j++) {
        int col = bn + warp_n + j * 8 + tig * 2;
        float b0 = bias[col], b1 = bias[col + 1];
#pragma unroll
        for (int i = 0; i < 4; i++) {
            int row = bm + warp_m + i * 16 + g;
            float2 v0 = make_float2(acc[i][j][0] + b0, acc[i][j][1] + b1);
            float2 v1 = make_float2(acc[i][j][2] + b0, acc[i][j][3] + b1);
            *reinterpret_cast<float2*>(C + (size_t)row * N + col) = v0;
            *reinterpret_cast<float2*>(C + (size_t)(row + 8) * N + col) = v1;
        }
    }
}

// ---------------------------------------------------------------------------
// Attention: one block per (b, t, h), 64 threads = one query row each.
// (unchanged from passing round-1/3 kernel)
// ---------------------------------------------------------------------------
__global__ __launch_bounds__(64) void attn_kernel(const float* __restrict__ rpb)
{
    __shared__ float4 sK[512];
    __shared__ float4 sV[512];
    __shared__ float  sL[64 * 65];

    const int bx = blockIdx.x;
    const int h = bx & 7;
    const int t = (bx >> 3) & 1;
    const int b = bx >> 4;
    const int n = threadIdx.x;

    const float* kb = g_kv + (size_t)((b * 2 + t) * 64) * 512 + h * 32;
    for (int i = n; i < 512; i += 64) {
        int r = i >> 3, c = i & 7;
        sK[i] = *reinterpret_cast<const float4*>(kb + (size_t)r * 512 + c * 4);
        sV[i] = *reinterpret_cast<const float4*>(kb + 256 + (size_t)r * 512 + c * 4);
    }

    const float scale = 0.17677669529663687f;  // 32^-0.5
    float q[32];
    const float* qb = g_q + (size_t)(b * 64 + n) * 256 + h * 32;
#pragma unroll
    for (int c = 0; c < 8; c++) {
        float4 f = *reinterpret_cast<const float4*>(qb + c * 4);
        q[4 * c + 0] = f.x * scale; q[4 * c + 1] = f.y * scale;
        q[4 * c + 2] = f.z * scale; q[4 * c + 3] = f.w * scale;
    }
    __syncthreads();

    const int base_idx = ((n >> 3) + 7) * 15 + ((n & 7) + 7);
    float mx = -1e30f;
    float* myL = &sL[n * 65];
#pragma unroll 4
    for (int m = 0; m < 64; m++) {
        const float4* kr = &sK[m * 8];
        float s0 = 0.f, s1 = 0.f, s2 = 0.f, s3 = 0.f;
#pragma unroll
        for (int c = 0; c < 8; c++) {
            float4 kf = kr[c];
            s0 = fmaf(q[4 * c + 0], kf.x, s0);
            s1 = fmaf(q[4 * c + 1], kf.y, s1);
            s2 = fmaf(q[4 * c + 2], kf.z, s2);
            s3 = fmaf(q[4 * c + 3], kf.w, s3);
        }
        int idx = base_idx - ((m >> 3) * 15 + (m & 7));
        float s = (s0 + s1) + (s2 + s3) + __ldg(&rpb[idx * 8 + h]);
        mx = fmaxf(mx, s);
        myL[m] = s;
    }

    float sum0 = 0.f, sum1 = 0.f;
#pragma unroll 4
    for (int m = 0; m < 64; m += 2) {
        float e0 = __expf(myL[m] - mx);
        float e1 = __expf(myL[m + 1] - mx);
        myL[m] = e0; myL[m + 1] = e1;
        sum0 += e0; sum1 += e1;
    }
    float inv = 1.0f / (sum0 + sum1);

    float o[32];
#pragma unroll
    for (int c = 0; c < 32; c++) o[c] = 0.f;
#pragma unroll 2
    for (int m = 0; m < 64; m++) {
        float w = myL[m];
        const float4* vr = &sV[m * 8];
#pragma unroll
        for (int c = 0; c < 8; c++) {
            float4 vf = vr[c];
            o[4 * c + 0] = fmaf(w, vf.x, o[4 * c + 0]);
            o[4 * c + 1] = fmaf(w, vf.y, o[4 * c + 1]);
            o[4 * c + 2] = fmaf(w, vf.z, o[4 * c + 2]);
            o[4 * c + 3] = fmaf(w, vf.w, o[4 * c + 3]);
        }
    }

    float* ob = g_attn + (size_t)((b * 2 + t) * 64 + n) * 256 + h * 32;
#pragma unroll
    for (int c = 0; c < 8; c++) {
        float4 v;
        v.x = o[4 * c + 0] * inv; v.y = o[4 * c + 1] * inv;
        v.z = o[4 * c + 2] * inv; v.w = o[4 * c + 3] * inv;
        *reinterpret_cast<float4*>(ob + c * 4) = v;
    }
}

// ---------------------------------------------------------------------------
extern "C" void kernel_launch(void* const* d_in, const int* in_sizes, int n_in,
                              void* d_out, int out_size)
{
    const float* x      = (const float*)d_in[0];
    const float* memory = (const float*)d_in[1];
    const float* q_w    = (const float*)d_in[2];
    const float* q_b    = (const float*)d_in[3];
    const float* kv_w   = (const float*)d_in[4];
    const float* kv_b   = (const float*)d_in[5];
    const float* proj_w = (const float*)d_in[6];
    const float* proj_b = (const float*)d_in[7];
    const float* rpb    = (const float*)d_in[8];
    float* out = (float*)d_out;

    float *pq, *pkv, *pattn;
    cudaGetSymbolAddress((void**)&pq, g_q);
    cudaGetSymbolAddress((void**)&pkv, g_kv);
    cudaGetSymbolAddress((void**)&pattn, g_attn);

    // q = x @ q_w^T + q_b              (131072 x 256, K=256)
    gemm_tf32<<<dim3(2, 1024), 256>>>(x, q_w, q_b, pq, BB * NTOK, CDIM, CDIM);
    // kv = memory @ kv_w^T + kv_b      (262144 x 512, K=256)
    gemm_tf32<<<dim3(4, 2048), 256>>>(memory, kv_w, kv_b, pkv, BB * TT * NTOK, 2 * CDIM, CDIM);
    // softmax attention per (b, t, h)
    attn_kernel<<<BB * TT * NH, 64>>>(rpb);
    // out = attn @ proj_w^T + proj_b   (262144 x 256, K=256)
    gemm_tf32<<<dim3(2, 2048), 256>>>(pattn, proj_w, proj_b, out, BB * TT * NTOK, CDIM, CDIM);
}

// round 7
// speedup vs baseline: 2.2384x; 1.0875x over previous
#include <cuda_runtime.h>
#include <cstdint>

// Problem constants
#define BB 2048
#define TT 2
#define NTOK 64
#define CDIM 256
#define NH 8
#define HD 32

// Scratch (device globals; allocation APIs are forbidden)
__device__ float g_q[(size_t)BB * NTOK * CDIM];
__device__ float g_kv[(size_t)BB * TT * NTOK * 2 * CDIM];
__device__ float g_attn[(size_t)BB * TT * NTOK * CDIM];

// ---- tf32 helpers -----------------------------------------------------------
__device__ __forceinline__ uint32_t f2tf32(float f) {
    uint32_t r;
    asm("cvt.rna.tf32.f32 %0, %1;" : "=r"(r) : "f"(f));
    return r;
}
__device__ __forceinline__ void split_tf32(float x, uint32_t& hi, uint32_t& lo) {
    hi = f2tf32(x);
    lo = f2tf32(x - __uint_as_float(hi));
}
__device__ __forceinline__ void mma_tf32(float c[4], const uint32_t a[4],
                                         const uint32_t b[2]) {
    asm("mma.sync.aligned.m16n8k8.row.col.f32.tf32.tf32.f32 "
        "{%0,%1,%2,%3}, {%4,%5,%6,%7}, {%8,%9}, {%0,%1,%2,%3};"
        : "+f"(c[0]), "+f"(c[1]), "+f"(c[2]), "+f"(c[3])
        : "r"(a[0]), "r"(a[1]), "r"(a[2]), "r"(a[3]), "r"(b[0]), "r"(b[1]));
}

// ---------------------------------------------------------------------------
// TF32 tensor-core GEMM: C[M,N] = A[M,K] @ W[N,K]^T + bias[N]  (unchanged)
// ---------------------------------------------------------------------------
__global__ __launch_bounds__(256, 2) void gemm_tf32(
    const float* __restrict__ A, const float* __restrict__ W,
    const float* __restrict__ bias, float* __restrict__ C,
    int M, int N, int K)
{
    __shared__ uint32_t As[128][36];
    __shared__ uint32_t Ws[128][36];

    const int tid  = threadIdx.x;
    const int wid  = tid >> 5;
    const int lane = tid & 31;
    const int g    = lane >> 2;
    const int tig  = lane & 3;
    const int bm = blockIdx.y * 128;
    const int bn = blockIdx.x * 128;
    const int warp_m = (wid & 1) * 64;
    const int warp_n = (wid >> 1) * 32;

    const int sr  = tid >> 3;
    const int sk4 = tid & 7;

    float acc[4][4][4];
#pragma unroll
    for (int i = 0; i < 4; i++)
#pragma unroll
        for (int j = 0; j < 4; j++)
#pragma unroll
            for (int r = 0; r < 4; r++) acc[i][j][r] = 0.0f;

    for (int k0 = 0; k0 < K; k0 += 32) {
#pragma unroll
        for (int it = 0; it < 4; it++) {
            int r = sr + it * 32;
            float4 a4 = *reinterpret_cast<const float4*>(
                A + (size_t)(bm + r) * K + k0 + sk4 * 4);
            float4 w4 = *reinterpret_cast<const float4*>(
                W + (size_t)(bn + r) * K + k0 + sk4 * 4);
            uint4 at = make_uint4(f2tf32(a4.x), f2tf32(a4.y), f2tf32(a4.z), f2tf32(a4.w));
            uint4 wt = make_uint4(f2tf32(w4.x), f2tf32(w4.y), f2tf32(w4.z), f2tf32(w4.w));
            *reinterpret_cast<uint4*>(&As[r][sk4 * 4]) = at;
            *reinterpret_cast<uint4*>(&Ws[r][sk4 * 4]) = wt;
        }
        __syncthreads();

#pragma unroll
        for (int kk = 0; kk < 4; kk++) {
            uint32_t af[4][4], bf[4][2];
            const int kb = kk * 8;
#pragma unroll
            for (int i = 0; i < 4; i++) {
                int row = warp_m + i * 16;
                af[i][0] = As[row + g][kb + tig];
                af[i][1] = As[row + g + 8][kb + tig];
                af[i][2] = As[row + g][kb + tig + 4];
                af[i][3] = As[row + g + 8][kb + tig + 4];
            }
#pragma unroll
            for (int j = 0; j < 4; j++) {
                int col = warp_n + j * 8 + g;
                bf[j][0] = Ws[col][kb + tig];
                bf[j][1] = Ws[col][kb + tig + 4];
            }
#pragma unroll
            for (int i = 0; i < 4; i++)
#pragma unroll
                for (int j = 0; j < 4; j++)
                    mma_tf32(acc[i][j], af[i], bf[j]);
        }
        __syncthreads();
    }

#pragma unroll
    for (int j = 0; j < 4; j++) {
        int col = bn + warp_n + j * 8 + tig * 2;
        float b0 = bias[col], b1 = bias[col + 1];
#pragma unroll
        for (int i = 0; i < 4; i++) {
            int row = bm + warp_m + i * 16 + g;
            float2 v0 = make_float2(acc[i][j][0] + b0, acc[i][j][1] + b1);
            float2 v1 = make_float2(acc[i][j][2] + b0, acc[i][j][3] + b1);
            *reinterpret_cast<float2*>(C + (size_t)row * N + col) = v0;
            *reinterpret_cast<float2*>(C + (size_t)(row + 8) * N + col) = v1;
        }
    }
}

// ---------------------------------------------------------------------------
// Tensor-core attention, 3xTF32 (compensated) QK^T and PV.
// Block = (b, t, head-pair): 128 threads, 2 warps per head (M split 32/32).
// Per-head smem (floats): Q[64x36] @0, K[64x36] @2304, V[64x40] @4608,
// S/P_hi[64x68] @7168, inv_sum[64] @11520.  P_lo overlays dead Q/K @0.
// ---------------------------------------------------------------------------
#define HEADF 11584
#define QOFF 0
#define KOFF 2304
#define VOFF 4608
#define SOFF 7168
#define SUMOFF 11520
#define PLOFF 0
#define ATTN_SMEM_BYTES (2 * HEADF * 4)

__global__ __launch_bounds__(128) void attn_mma(const float* __restrict__ rpb)
{
    extern __shared__ float sm[];
    const int tid  = threadIdx.x;
    const int wid  = tid >> 5;
    const int lane = tid & 31;
    const int g    = lane >> 2;
    const int tig  = lane & 3;
    const int hslot = wid >> 1;   // head within block (0/1)
    const int whalf = wid & 1;    // M-half within head
    const int bx = blockIdx.x;
    const int hpair = bx & 3;
    const int t = (bx >> 2) & 1;
    const int b = bx >> 3;
    const int h = hpair * 2 + hslot;
    const int th = tid & 63;      // thread id within head (0..63)

    float* S = sm + hslot * HEADF;

    // ---- stage Q (pre-scaled), K, V ----
    const float scale = 0.17677669529663687f;  // 32^-0.5
    const float* qg = g_q + (size_t)(b * 64) * 256 + h * 32;
    const float* kg = g_kv + (size_t)((b * 2 + t) * 64) * 512 + h * 32;
#pragma unroll
    for (int it = 0; it < 8; it++) {
        int idx = th + 64 * it;         // 0..511 float4s
        int r = idx >> 3, c4 = idx & 7;
        float4 qv = *reinterpret_cast<const float4*>(qg + (size_t)r * 256 + c4 * 4);
        qv.x *= scale; qv.y *= scale; qv.z *= scale; qv.w *= scale;
        *reinterpret_cast<float4*>(S + QOFF + r * 36 + c4 * 4) = qv;
        float4 kv = *reinterpret_cast<const float4*>(kg + (size_t)r * 512 + c4 * 4);
        *reinterpret_cast<float4*>(S + KOFF + r * 36 + c4 * 4) = kv;
        float4 vv = *reinterpret_cast<const float4*>(kg + 256 + (size_t)r * 512 + c4 * 4);
        *reinterpret_cast<float4*>(S + VOFF + r * 40 + c4 * 4) = vv;
    }
    __syncthreads();

    // ---- QK^T : S[64x64] = Q @ K^T, warp handles rows 32*whalf..+31 ----
#pragma unroll
    for (int jh = 0; jh < 2; jh++) {
        float acc[2][4][4];
#pragma unroll
        for (int i = 0; i < 2; i++)
#pragma unroll
            for (int j = 0; j < 4; j++)
#pragma unroll
                for (int r = 0; r < 4; r++) acc[i][j][r] = 0.0f;

#pragma unroll
        for (int k = 0; k < 4; k++) {
            uint32_t ah[2][4], al[2][4];
#pragma unroll
            for (int i = 0; i < 2; i++) {
                int rb = (2 * whalf + i) * 16;
                const float* q0 = S + QOFF + (rb + g) * 36 + 8 * k + tig;
                const float* q1 = S + QOFF + (rb + 8 + g) * 36 + 8 * k + tig;
                split_tf32(q0[0], ah[i][0], al[i][0]);
                split_tf32(q1[0], ah[i][1], al[i][1]);
                split_tf32(q0[4], ah[i][2], al[i][2]);
                split_tf32(q1[4], ah[i][3], al[i][3]);
            }
            uint32_t bh[4][2], bl[4][2];
#pragma unroll
            for (int j = 0; j < 4; j++) {
                int col = (jh * 4 + j) * 8 + g;
                const float* kp = S + KOFF + col * 36 + 8 * k + tig;
                split_tf32(kp[0], bh[j][0], bl[j][0]);
                split_tf32(kp[4], bh[j][1], bl[j][1]);
            }
#pragma unroll
            for (int i = 0; i < 2; i++)
#pragma unroll
                for (int j = 0; j < 4; j++) {
                    mma_tf32(acc[i][j], ah[i], bh[j]);
                    mma_tf32(acc[i][j], al[i], bh[j]);
                    mma_tf32(acc[i][j], ah[i], bl[j]);
                }
        }
#pragma unroll
        for (int i = 0; i < 2; i++)
#pragma unroll
            for (int j = 0; j < 4; j++) {
                int rb = (2 * whalf + i) * 16;
                int cb = (jh * 4 + j) * 8 + 2 * tig;
                *reinterpret_cast<float2*>(S + SOFF + (rb + g) * 68 + cb) =
                    make_float2(acc[i][j][0], acc[i][j][1]);
                *reinterpret_cast<float2*>(S + SOFF + (rb + 8 + g) * 68 + cb) =
                    make_float2(acc[i][j][2], acc[i][j][3]);
            }
    }
    __syncthreads();

    // ---- softmax: one row per thread; write P_hi (in S) and P_lo ----
    {
        const int r = th;
        const int rI = r >> 3, rJ = r & 7;
        float* Sr = S + SOFF + r * 68;
        float mx = -1e30f;
#pragma unroll 8
        for (int m = 0; m < 64; m++) {
            int idx = (rI - (m >> 3) + 7) * 15 + (rJ - (m & 7) + 7);
            float s = Sr[m] + __ldg(&rpb[idx * 8 + h]);
            Sr[m] = s;
            mx = fmaxf(mx, s);
        }
        float sum = 0.0f;
        float* Pl = S + PLOFF + r * 68;
#pragma unroll 8
        for (int m = 0; m < 64; m++) {
            float e = __expf(Sr[m] - mx);
            sum += e;
            uint32_t hi = f2tf32(e);
            Sr[m] = __uint_as_float(hi);
            Pl[m] = __uint_as_float(f2tf32(e - __uint_as_float(hi)));
        }
        S[SUMOFF + r] = 1.0f / sum;
    }
    __syncthreads();

    // ---- PV : O[64x32] = P @ V ----
    float acc[2][4][4];
#pragma unroll
    for (int i = 0; i < 2; i++)
#pragma unroll
        for (int j = 0; j < 4; j++)
#pragma unroll
            for (int r = 0; r < 4; r++) acc[i][j][r] = 0.0f;

#pragma unroll
    for (int k = 0; k < 8; k++) {
        uint32_t ah[2][4], al[2][4];
#pragma unroll
        for (int i = 0; i < 2; i++) {
            int rb = (2 * whalf + i) * 16;
            const float* p0 = S + SOFF + (rb + g) * 68 + 8 * k + tig;
            const float* p1 = S + SOFF + (rb + 8 + g) * 68 + 8 * k + tig;
            const float* l0 = S + PLOFF + (rb + g) * 68 + 8 * k + tig;
            const float* l1 = S + PLOFF + (rb + 8 + g) * 68 + 8 * k + tig;
            ah[i][0] = __float_as_uint(p0[0]); al[i][0] = __float_as_uint(l0[0]);
            ah[i][1] = __float_as_uint(p1[0]); al[i][1] = __float_as_uint(l1[0]);
            ah[i][2] = __float_as_uint(p0[4]); al[i][2] = __float_as_uint(l0[4]);
            ah[i][3] = __float_as_uint(p1[4]); al[i][3] = __float_as_uint(l1[4]);
        }
        uint32_t bh[4][2], bl[4][2];
#pragma unroll
        for (int j = 0; j < 4; j++) {
            const float* v0 = S + VOFF + (8 * k + tig) * 40 + 8 * j + g;
            const float* v1 = S + VOFF + (8 * k + tig + 4) * 40 + 8 * j + g;
            split_tf32(v0[0], bh[j][0], bl[j][0]);
            split_tf32(v1[0], bh[j][1], bl[j][1]);
        }
#pragma unroll
        for (int i = 0; i < 2; i++)
#pragma unroll
            for (int j = 0; j < 4; j++) {
                mma_tf32(acc[i][j], ah[i], bh[j]);
                mma_tf32(acc[i][j], al[i], bh[j]);
                mma_tf32(acc[i][j], ah[i], bl[j]);
            }
    }

    // ---- epilogue: scale by 1/sum and store ----
    float* og = g_attn + (size_t)((b * 2 + t) * 64) * 256 + h * 32;
#pragma unroll
    for (int i = 0; i < 2; i++) {
        int rb = (2 * whalf + i) * 16;
        float is0 = S[SUMOFF + rb + g];
        float is1 = S[SUMOFF + rb + 8 + g];
#pragma unroll
        for (int j = 0; j < 4; j++) {
            int d = 8 * j + 2 * tig;
            *reinterpret_cast<float2*>(og + (size_t)(rb + g) * 256 + d) =
                make_float2(acc[i][j][0] * is0, acc[i][j][1] * is0);
            *reinterpret_cast<float2*>(og + (size_t)(rb + 8 + g) * 256 + d) =
                make_float2(acc[i][j][2] * is1, acc[i][j][3] * is1);
        }
    }
}

// ---------------------------------------------------------------------------
extern "C" void kernel_launch(void* const* d_in, const int* in_sizes, int n_in,
                              void* d_out, int out_size)
{
    const float* x      = (const float*)d_in[0];
    const float* memory = (const float*)d_in[1];
    const float* q_w    = (const float*)d_in[2];
    const float* q_b    = (const float*)d_in[3];
    const float* kv_w   = (const float*)d_in[4];
    const float* kv_b   = (const float*)d_in[5];
    const float* proj_w = (const float*)d_in[6];
    const float* proj_b = (const float*)d_in[7];
    const float* rpb    = (const float*)d_in[8];
    float* out = (float*)d_out;

    float *pq, *pkv, *pattn;
    cudaGetSymbolAddress((void**)&pq, g_q);
    cudaGetSymbolAddress((void**)&pkv, g_kv);
    cudaGetSymbolAddress((void**)&pattn, g_attn);

    cudaFuncSetAttribute(attn_mma, cudaFuncAttributeMaxDynamicSharedMemorySize,
                         ATTN_SMEM_BYTES);

    // q = x @ q_w^T + q_b              (131072 x 256, K=256)
    gemm_tf32<<<dim3(2, 1024), 256>>>(x, q_w, q_b, pq, BB * NTOK, CDIM, CDIM);
    // kv = memory @ kv_w^T + kv_b      (262144 x 512, K=256)
    gemm_tf32<<<dim3(4, 2048), 256>>>(memory, kv_w, kv_b, pkv, BB * TT * NTOK, 2 * CDIM, CDIM);
    // attention: block = (b, t, head-pair)
    attn_mma<<<BB * TT * (NH / 2), 128, ATTN_SMEM_BYTES>>>(rpb);
    // out = attn @ proj_w^T + proj_b   (262144 x 256, K=256)
    gemm_tf32<<<dim3(2, 2048), 256>>>(pattn, proj_w, proj_b, out, BB * TT * NTOK, CDIM, CDIM);
}

// round 8
// speedup vs baseline: 2.8629x; 1.2790x over previous
#include <cuda_runtime.h>
#include <cstdint>

// Problem constants
#define BB 2048
#define TT 2
#define NTOK 64
#define CDIM 256
#define NH 8
#define HD 32

// Scratch (device globals; allocation APIs are forbidden)
__device__ float g_q[(size_t)BB * NTOK * CDIM];
__device__ float g_kv[(size_t)BB * TT * NTOK * 2 * CDIM];
__device__ float g_attn[(size_t)BB * TT * NTOK * CDIM];
__device__ float g_bias[NH * NTOK * NTOK];   // [h][n][m] precomputed rpb

// ---- tf32 helpers -----------------------------------------------------------
__device__ __forceinline__ uint32_t f2tf32(float f) {
    uint32_t r;
    asm("cvt.rna.tf32.f32 %0, %1;" : "=r"(r) : "f"(f));
    return r;
}
__device__ __forceinline__ void split_tf32(float x, uint32_t& hi, uint32_t& lo) {
    hi = f2tf32(x);
    lo = f2tf32(x - __uint_as_float(hi));
}
__device__ __forceinline__ void mma_tf32(float c[4], const uint32_t a[4],
                                         const uint32_t b[2]) {
    asm("mma.sync.aligned.m16n8k8.row.col.f32.tf32.tf32.f32 "
        "{%0,%1,%2,%3}, {%4,%5,%6,%7}, {%8,%9}, {%0,%1,%2,%3};"
        : "+f"(c[0]), "+f"(c[1]), "+f"(c[2]), "+f"(c[3])
        : "r"(a[0]), "r"(a[1]), "r"(a[2]), "r"(a[3]), "r"(b[0]), "r"(b[1]));
}

// ---- cp.async helpers -------------------------------------------------------
__device__ __forceinline__ void cp16(float* smem_dst, const float* gsrc) {
    uint32_t s = (uint32_t)__cvta_generic_to_shared(smem_dst);
    asm volatile("cp.async.cg.shared.global [%0], [%1], 16;" :: "r"(s), "l"(gsrc));
}
__device__ __forceinline__ void cp_commit() {
    asm volatile("cp.async.commit_group;");
}
__device__ __forceinline__ void cp_wait1() {
    asm volatile("cp.async.wait_group 1;");
}
__device__ __forceinline__ void cp_wait0() {
    asm volatile("cp.async.wait_group 0;");
}

// ---------------------------------------------------------------------------
// Bias precompute: g_bias[h][n][m] = rpb[relidx(n,m)*8 + h]
// ---------------------------------------------------------------------------
__global__ __launch_bounds__(256) void bias_precomp(const float* __restrict__ rpb)
{
    int i = blockIdx.x * 256 + threadIdx.x;   // 0..32767
    int h = i >> 12;
    int n = (i >> 6) & 63;
    int m = i & 63;
    int idx = ((n >> 3) - (m >> 3) + 7) * 15 + ((n & 7) - (m & 7) + 7);
    g_bias[i] = rpb[idx * 8 + h];
}

// ---------------------------------------------------------------------------
// TF32 GEMM with cp.async double buffering:
// C[M,N] = A[M,K] @ W[N,K]^T + bias[N].  128x128 tile, BK=32, 256 threads.
// Raw fp32 staged in smem (stride 36, 16B-aligned rows); cvt at fragment load.
// ---------------------------------------------------------------------------
#define GEMM_SMEM_BYTES (4 * 128 * 36 * 4)   // 2 bufs x (A + W) tiles

__global__ __launch_bounds__(256, 2) void gemm_tf32(
    const float* __restrict__ A, const float* __restrict__ W,
    const float* __restrict__ bias, float* __restrict__ C,
    int M, int N, int K)
{
    extern __shared__ float gsm[];
    float* Asm = gsm;                    // [2][128*36]
    float* Wsm = gsm + 2 * 128 * 36;     // [2][128*36]

    const int tid  = threadIdx.x;
    const int wid  = tid >> 5;
    const int lane = tid & 31;
    const int g    = lane >> 2;
    const int tig  = lane & 3;
    const int bm = blockIdx.y * 128;
    const int bn = blockIdx.x * 128;
    const int warp_m = (wid & 1) * 64;
    const int warp_n = (wid >> 1) * 32;

    const int sr  = tid >> 3;   // 0..31
    const int sk4 = tid & 7;    // 0..7

    const float* Abase = A + (size_t)(bm + sr) * K + sk4 * 4;
    const float* Wbase = W + (size_t)(bn + sr) * K + sk4 * 4;

    float acc[4][4][4];
#pragma unroll
    for (int i = 0; i < 4; i++)
#pragma unroll
        for (int j = 0; j < 4; j++)
#pragma unroll
            for (int r = 0; r < 4; r++) acc[i][j][r] = 0.0f;

    const int nk = K >> 5;

    // prologue: stage tile 0 into buffer 0
    {
        float* Ad = Asm;
        float* Wd = Wsm;
#pragma unroll
        for (int it = 0; it < 4; it++) {
            int row = sr + it * 32;
            cp16(Ad + row * 36 + sk4 * 4, Abase + (size_t)(it * 32) * K);
            cp16(Wd + row * 36 + sk4 * 4, Wbase + (size_t)(it * 32) * K);
        }
        cp_commit();
    }

    for (int kt = 0; kt < nk; kt++) {
        const int cur = kt & 1;
        if (kt + 1 < nk) {
            float* Ad = Asm + (1 - cur) * 128 * 36;
            float* Wd = Wsm + (1 - cur) * 128 * 36;
            const float* Ag = Abase + (kt + 1) * 32;
            const float* Wg = Wbase + (kt + 1) * 32;
#pragma unroll
            for (int it = 0; it < 4; it++) {
                int row = sr + it * 32;
                cp16(Ad + row * 36 + sk4 * 4, Ag + (size_t)(it * 32) * K);
                cp16(Wd + row * 36 + sk4 * 4, Wg + (size_t)(it * 32) * K);
            }
            cp_commit();
            cp_wait1();
        } else {
            cp_wait0();
        }
        __syncthreads();

        const float* Ab = Asm + cur * 128 * 36;
        const float* Wb = Wsm + cur * 128 * 36;
#pragma unroll
        for (int kk = 0; kk < 4; kk++) {
            const int kb = kk * 8;
            uint32_t af[4][4], bf[4][2];
#pragma unroll
            for (int i = 0; i < 4; i++) {
                int row = warp_m + i * 16;
                af[i][0] = f2tf32(Ab[(row + g) * 36 + kb + tig]);
                af[i][1] = f2tf32(Ab[(row + 8 + g) * 36 + kb + tig]);
                af[i][2] = f2tf32(Ab[(row + g) * 36 + kb + tig + 4]);
                af[i][3] = f2tf32(Ab[(row + 8 + g) * 36 + kb + tig + 4]);
            }
#pragma unroll
            for (int j = 0; j < 4; j++) {
                int col = warp_n + j * 8 + g;
                bf[j][0] = f2tf32(Wb[col * 36 + kb + tig]);
                bf[j][1] = f2tf32(Wb[col * 36 + kb + tig + 4]);
            }
#pragma unroll
            for (int i = 0; i < 4; i++)
#pragma unroll
                for (int j = 0; j < 4; j++)
                    mma_tf32(acc[i][j], af[i], bf[j]);
        }
        __syncthreads();
    }

#pragma unroll
    for (int j = 0; j < 4; j++) {
        int col = bn + warp_n + j * 8 + tig * 2;
        float b0 = bias[col], b1 = bias[col + 1];
#pragma unroll
        for (int i = 0; i < 4; i++) {
            int row = bm + warp_m + i * 16 + g;
            float2 v0 = make_float2(acc[i][j][0] + b0, acc[i][j][1] + b1);
            float2 v1 = make_float2(acc[i][j][2] + b0, acc[i][j][3] + b1);
            *reinterpret_cast<float2*>(C + (size_t)row * N + col) = v0;
            *reinterpret_cast<float2*>(C + (size_t)(row + 8) * N + col) = v1;
        }
    }
}

// ---------------------------------------------------------------------------
// Tensor-core attention, 3xTF32 QK^T and PV.
// Block = (b, t, head-pair): 128 threads, 2 warps per head.
// Per-head smem (floats): Q[64x36] @0, K[64x36] @2304, V[64x40] @4608,
// S/P_hi[64x68] @7168, inv_sum[64] @11520.
// Bias staged (then P_lo) overlays dead Q/K region @0.
// ---------------------------------------------------------------------------
#define HEADF 11584
#define QOFF 0
#define KOFF 2304
#define VOFF 4608
#define SOFF 7168
#define SUMOFF 11520
#define PLOFF 0
#define ATTN_SMEM_BYTES (2 * HEADF * 4)

__global__ __launch_bounds__(128) void attn_mma(void)
{
    extern __shared__ float sm[];
    const int tid  = threadIdx.x;
    const int wid  = tid >> 5;
    const int lane = tid & 31;
    const int g    = lane >> 2;
    const int tig  = lane & 3;
    const int hslot = wid >> 1;
    const int whalf = wid & 1;
    const int bx = blockIdx.x;
    const int hpair = bx & 3;
    const int t = (bx >> 2) & 1;
    const int b = bx >> 3;
    const int h = hpair * 2 + hslot;
    const int th = tid & 63;

    float* S = sm + hslot * HEADF;

    // ---- stage Q (pre-scaled), K, V ----
    const float scale = 0.17677669529663687f;  // 32^-0.5
    const float* qg = g_q + (size_t)(b * 64) * 256 + h * 32;
    const float* kg = g_kv + (size_t)((b * 2 + t) * 64) * 512 + h * 32;
#pragma unroll
    for (int it = 0; it < 8; it++) {
        int idx = th + 64 * it;
        int r = idx >> 3, c4 = idx & 7;
        float4 qv = *reinterpret_cast<const float4*>(qg + (size_t)r * 256 + c4 * 4);
        qv.x *= scale; qv.y *= scale; qv.z *= scale; qv.w *= scale;
        *reinterpret_cast<float4*>(S + QOFF + r * 36 + c4 * 4) = qv;
        float4 kv = *reinterpret_cast<const float4*>(kg + (size_t)r * 512 + c4 * 4);
        *reinterpret_cast<float4*>(S + KOFF + r * 36 + c4 * 4) = kv;
        float4 vv = *reinterpret_cast<const float4*>(kg + 256 + (size_t)r * 512 + c4 * 4);
        *reinterpret_cast<float4*>(S + VOFF + r * 40 + c4 * 4) = vv;
    }
    __syncthreads();

    // ---- QK^T : S[64x64] = Q @ K^T; warp rows 32*whalf..+31, all 64 cols ----
    {
        float acc[2][8][4];
#pragma unroll
        for (int i = 0; i < 2; i++)
#pragma unroll
            for (int j = 0; j < 8; j++)
#pragma unroll
                for (int r = 0; r < 4; r++) acc[i][j][r] = 0.0f;

#pragma unroll
        for (int k = 0; k < 4; k++) {
            uint32_t ah[2][4], al[2][4];
#pragma unroll
            for (int i = 0; i < 2; i++) {
                int rb = (2 * whalf + i) * 16;
                const float* q0 = S + QOFF + (rb + g) * 36 + 8 * k + tig;
                const float* q1 = S + QOFF + (rb + 8 + g) * 36 + 8 * k + tig;
                split_tf32(q0[0], ah[i][0], al[i][0]);
                split_tf32(q1[0], ah[i][1], al[i][1]);
                split_tf32(q0[4], ah[i][2], al[i][2]);
                split_tf32(q1[4], ah[i][3], al[i][3]);
            }
#pragma unroll
            for (int jn = 0; jn < 8; jn++) {
                int col = jn * 8 + g;
                const float* kp = S + KOFF + col * 36 + 8 * k + tig;
                uint32_t bh[2], bl[2];
                split_tf32(kp[0], bh[0], bl[0]);
                split_tf32(kp[4], bh[1], bl[1]);
#pragma unroll
                for (int i = 0; i < 2; i++) {
                    mma_tf32(acc[i][jn], ah[i], bh);
                    mma_tf32(acc[i][jn], al[i], bh);
                    mma_tf32(acc[i][jn], ah[i], bl);
                }
            }
        }
#pragma unroll
        for (int i = 0; i < 2; i++)
#pragma unroll
            for (int jn = 0; jn < 8; jn++) {
                int rb = (2 * whalf + i) * 16;
                int cb = jn * 8 + 2 * tig;
                *reinterpret_cast<float2*>(S + SOFF + (rb + g) * 68 + cb) =
                    make_float2(acc[i][jn][0], acc[i][jn][1]);
                *reinterpret_cast<float2*>(S + SOFF + (rb + 8 + g) * 68 + cb) =
                    make_float2(acc[i][jn][2], acc[i][jn][3]);
            }
    }
    __syncthreads();

    // ---- stage bias[h] (16KB) into P_lo region (coalesced float4) ----
    {
        const float* bg = g_bias + h * 4096;
#pragma unroll
        for (int it = 0; it < 16; it++) {
            int j = th + 64 * it;        // float4 id 0..1023
            int r = j >> 4, m4 = j & 15;
            float4 bv = *reinterpret_cast<const float4*>(bg + r * 64 + m4 * 4);
            *reinterpret_cast<float4*>(S + PLOFF + r * 68 + m4 * 4) = bv;
        }
    }
    __syncthreads();

    // ---- softmax: one row per thread (bias from smem) ----
    {
        const int r = th;
        float* Sr = S + SOFF + r * 68;
        float* Pl = S + PLOFF + r * 68;
        float mx = -1e30f;
#pragma unroll 8
        for (int m = 0; m < 64; m++) {
            float s = Sr[m] + Pl[m];
            Sr[m] = s;
            mx = fmaxf(mx, s);
        }
        float sum = 0.0f;
#pragma unroll 8
        for (int m = 0; m < 64; m++) {
            float e = __expf(Sr[m] - mx);
            sum += e;
            uint32_t hi = f2tf32(e);
            Sr[m] = __uint_as_float(hi);
            Pl[m] = __uint_as_float(f2tf32(e - __uint_as_float(hi)));
        }
        S[SUMOFF + r] = 1.0f / sum;
    }
    __syncthreads();

    // ---- PV : O[64x32] = P @ V ----
    float acc[2][4][4];
#pragma unroll
    for (int i = 0; i < 2; i++)
#pragma unroll
        for (int j = 0; j < 4; j++)
#pragma unroll
            for (int r = 0; r < 4; r++) acc[i][j][r] = 0.0f;

#pragma unroll
    for (int k = 0; k < 8; k++) {
        uint32_t ah[2][4], al[2][4];
#pragma unroll
        for (int i = 0; i < 2; i++) {
            int rb = (2 * whalf + i) * 16;
            const float* p0 = S + SOFF + (rb + g) * 68 + 8 * k + tig;
            const float* p1 = S + SOFF + (rb + 8 + g) * 68 + 8 * k + tig;
            const float* l0 = S + PLOFF + (rb + g) * 68 + 8 * k + tig;
            const float* l1 = S + PLOFF + (rb + 8 + g) * 68 + 8 * k + tig;
            ah[i][0] = __float_as_uint(p0[0]); al[i][0] = __float_as_uint(l0[0]);
            ah[i][1] = __float_as_uint(p1[0]); al[i][1] = __float_as_uint(l1[0]);
            ah[i][2] = __float_as_uint(p0[4]); al[i][2] = __float_as_uint(l0[4]);
            ah[i][3] = __float_as_uint(p1[4]); al[i][3] = __float_as_uint(l1[4]);
        }
        uint32_t bh[4][2], bl[4][2];
#pragma unroll
        for (int j = 0; j < 4; j++) {
            const float* v0 = S + VOFF + (8 * k + tig) * 40 + 8 * j + g;
            const float* v1 = S + VOFF + (8 * k + tig + 4) * 40 + 8 * j + g;
            split_tf32(v0[0], bh[j][0], bl[j][0]);
            split_tf32(v1[0], bh[j][1], bl[j][1]);
        }
#pragma unroll
        for (int i = 0; i < 2; i++)
#pragma unroll
            for (int j = 0; j < 4; j++) {
                mma_tf32(acc[i][j], ah[i], bh[j]);
                mma_tf32(acc[i][j], al[i], bh[j]);
                mma_tf32(acc[i][j], ah[i], bl[j]);
            }
    }

    // ---- epilogue ----
    float* og = g_attn + (size_t)((b * 2 + t) * 64) * 256 + h * 32;
#pragma unroll
    for (int i = 0; i < 2; i++) {
        int rb = (2 * whalf + i) * 16;
        float is0 = S[SUMOFF + rb + g];
        float is1 = S[SUMOFF + rb + 8 + g];
#pragma unroll
        for (int j = 0; j < 4; j++) {
            int d = 8 * j + 2 * tig;
            *reinterpret_cast<float2*>(og + (size_t)(rb + g) * 256 + d) =
                make_float2(acc[i][j][0] * is0, acc[i][j][1] * is0);
            *reinterpret_cast<float2*>(og + (size_t)(rb + 8 + g) * 256 + d) =
                make_float2(acc[i][j][2] * is1, acc[i][j][3] * is1);
        }
    }
}

// ---------------------------------------------------------------------------
extern "C" void kernel_launch(void* const* d_in, const int* in_sizes, int n_in,
                              void* d_out, int out_size)
{
    const float* x      = (const float*)d_in[0];
    const float* memory = (const float*)d_in[1];
    const float* q_w    = (const float*)d_in[2];
    const float* q_b    = (const float*)d_in[3];
    const float* kv_w   = (const float*)d_in[4];
    const float* kv_b   = (const float*)d_in[5];
    const float* proj_w = (const float*)d_in[6];
    const float* proj_b = (const float*)d_in[7];
    const float* rpb    = (const float*)d_in[8];
    float* out = (float*)d_out;

    float *pq, *pkv, *pattn;
    cudaGetSymbolAddress((void**)&pq, g_q);
    cudaGetSymbolAddress((void**)&pkv, g_kv);
    cudaGetSymbolAddress((void**)&pattn, g_attn);

    cudaFuncSetAttribute(gemm_tf32, cudaFuncAttributeMaxDynamicSharedMemorySize,
                         GEMM_SMEM_BYTES);
    cudaFuncSetAttribute(attn_mma, cudaFuncAttributeMaxDynamicSharedMemorySize,
                         ATTN_SMEM_BYTES);

    bias_precomp<<<128, 256>>>(rpb);
    // q = x @ q_w^T + q_b              (131072 x 256, K=256)
    gemm_tf32<<<dim3(2, 1024), 256, GEMM_SMEM_BYTES>>>(x, q_w, q_b, pq, BB * NTOK, CDIM, CDIM);
    // kv = memory @ kv_w^T + kv_b      (262144 x 512, K=256)
    gemm_tf32<<<dim3(4, 2048), 256, GEMM_SMEM_BYTES>>>(memory, kv_w, kv_b, pkv, BB * TT * NTOK, 2 * CDIM, CDIM);
    // attention: block = (b, t, head-pair)
    attn_mma<<<BB * TT * (NH / 2), 128, ATTN_SMEM_BYTES>>>();
    // out = attn @ proj_w^T + proj_b   (262144 x 256, K=256)
    gemm_tf32<<<dim3(2, 2048), 256, GEMM_SMEM_BYTES>>>(pattn, proj_w, proj_b, out, BB * TT * NTOK, CDIM, CDIM);
}